// round 15
// baseline (speedup 1.0000x reference)
#include <cuda_runtime.h>
#include <cuda_fp16.h>
#include <cstdint>
#include <math.h>

// ---------------- problem shape ----------------------------------------------
#define B_   2
#define S_   2048
#define D_   1024
#define H_   16
#define HD   64
#define MTOT (B_*S_)          // 4096
// 1/sqrt(64) * log2(e): scores produced directly in log2 domain for exp2f
#define QSCALE (0.125f * 1.44269504088896f)

// ---------------- baseline-PTX helpers (compile at compute_103) --------------
__device__ __forceinline__ uint32_t smem_u32(const void* p) {
    uint32_t a;
    asm("{ .reg .u64 t; cvta.to.shared.u64 t, %1; cvt.u32.u64 %0, t; }"
        : "=r"(a) : "l"(p));
    return a;
}
#define CP_ASYNC16(dst, src) \
    asm volatile("cp.async.cg.shared.global [%0], [%1], 16;" :: "r"(dst), "l"(src))
#define CP_COMMIT() asm volatile("cp.async.commit_group;" ::: "memory")
#define CP_WAIT2()  asm volatile("cp.async.wait_group 2;" ::: "memory")
#define CP_WAIT1()  asm volatile("cp.async.wait_group 1;" ::: "memory")
#define CP_WAIT0()  asm volatile("cp.async.wait_group 0;" ::: "memory")

__device__ __forceinline__ void ldsm4(uint32_t& r0, uint32_t& r1,
                                      uint32_t& r2, uint32_t& r3, uint32_t a) {
    asm volatile("ldmatrix.sync.aligned.m8n8.x4.shared.b16 {%0,%1,%2,%3}, [%4];"
                 : "=r"(r0), "=r"(r1), "=r"(r2), "=r"(r3) : "r"(a));
}
__device__ __forceinline__ void ldsm4t(uint32_t& r0, uint32_t& r1,
                                       uint32_t& r2, uint32_t& r3, uint32_t a) {
    asm volatile("ldmatrix.sync.aligned.m8n8.x4.trans.shared.b16 {%0,%1,%2,%3}, [%4];"
                 : "=r"(r0), "=r"(r1), "=r"(r2), "=r"(r3) : "r"(a));
}
__device__ __forceinline__ void mma_f16(float* c,
    uint32_t a0, uint32_t a1, uint32_t a2, uint32_t a3, uint32_t b0, uint32_t b1) {
    asm volatile("mma.sync.aligned.m16n8k16.row.col.f32.f16.f16.f32 "
                 "{%0,%1,%2,%3}, {%4,%5,%6,%7}, {%8,%9}, {%0,%1,%2,%3};"
                 : "+f"(c[0]), "+f"(c[1]), "+f"(c[2]), "+f"(c[3])
                 : "r"(a0), "r"(a1), "r"(a2), "r"(a3), "r"(b0), "r"(b1));
}
__device__ __forceinline__ uint32_t pack_h2(float a, float b) {
    __half2 t = __floats2half2_rn(a, b);
    return *(uint32_t*)&t;
}

// ---------------- scratch (device globals; no allocations allowed) ----------
__device__ __half g_q  [(size_t)B_*H_*S_*HD];
__device__ __half g_k  [(size_t)B_*H_*S_*HD];
__device__ __half g_v  [(size_t)B_*H_*S_*HD];
__device__ __half g_xh [(size_t)MTOT*D_];
__device__ __half g_wh [(size_t)4*D_*D_];                        // Wq|Wk|Wv|Wo
__device__ __half g_att[(size_t)MTOT*D_];
__device__ float2 g_rope[(size_t)S_*32];          // (cos,sin) per (spos, d/2)

// ---------------- fused fp32->fp16 convert (x + 4 W) + RoPE table ------------
#define RW  ((D_*D_)/4)        // 262144 float4 per weight
#define NCVT (8*RW)
#define NROPE (S_*32)
__global__ void split_all(const float* __restrict__ x,
                          const float* __restrict__ w0, const float* __restrict__ w1,
                          const float* __restrict__ w2, const float* __restrict__ w3,
                          __half* __restrict__ xh, __half* __restrict__ wh,
                          float2* __restrict__ ropet)
{
    int i = blockIdx.x * blockDim.x + threadIdx.x;
    if (i >= NCVT) {
        int j = i - NCVT;
        if (j < NROPE) {
            int spos = j >> 5, d2 = j & 31;
            float theta = powf(10000.0f, -2.0f * (float)d2 / (float)HD);
            float ang = (float)spos * theta;
            float ss, cc;
            sincosf(ang, &ss, &cc);
            ropet[j] = make_float2(cc, ss);
        }
        return;
    }
    const float* src;
    __half* hi;
    int local;
    if (i < 4 * RW) {
        src = x; hi = xh; local = i;
    } else {
        int ip = i - 4 * RW;
        int r  = ip >> 18;     // RW = 2^18
        local  = ip & (RW - 1);
        src = (r == 0) ? w0 : (r == 1) ? w1 : (r == 2) ? w2 : w3;
        hi = wh + (size_t)r * D_ * D_;
    }
    float4 v = ((const float4*)src)[local];
    __half2 a = __floats2half2_rn(v.x, v.y);
    __half2 b = __floats2half2_rn(v.z, v.w);
    ((__half2*)hi)[2*local]   = a;
    ((__half2*)hi)[2*local+1] = b;
}

// ---------------- shared 128B-row swizzle ------------------------------------
__device__ __forceinline__ uint32_t fsw(int row, int c) {   // c in 0..7 (16B)
    return (uint32_t)(row * 128 + ((c ^ (row & 7)) << 4));
}

// ---------------- HMMA GEMM (3-stage, BK=64): C = A W^T ----------------------
// Plain fp16, 1 MMA per fragment. Stage = A(16K)|B(16K) = 32KB, 3 stages =
// 96KB -> 2 CTAs/SM (192KB smem, 127 regs). Prefetch distance 2.
#define BKG 64
#define NKI (D_/BKG)       // 16
#define STG 32768          // bytes per stage
#define GSMEM (3*STG)      // 96 KB

__device__ __forceinline__ void stage_load(
    uint32_t sb, int s, int k0, int tid, int m0, int n0,
    const __half* __restrict__ A, const __half* __restrict__ B)
{
    const uint32_t base = sb + (uint32_t)s * STG;
#pragma unroll
    for (int p = 0; p < 4; p++) {
        const int gi  = tid + p * 256;       // 0..1023
        const int row = gi >> 3;             // 0..127
        const int c   = gi & 7;
        const uint32_t so = fsw(row, c);
        CP_ASYNC16(base + 0     + so, A + (size_t)(m0 + row) * D_ + k0 + c * 8);
        CP_ASYNC16(base + 16384 + so, B + (size_t)(n0 + row) * D_ + k0 + c * 8);
    }
}

// QKV=1: n0 in [0,3072): B = Wq|Wk|Wv rows; RoPE/scale + fp16 scatter.
// QKV=0: n0 in [0,1024): B = Wo rows; fp32 [M,D] output.
template<int QKV>
__global__ __launch_bounds__(256, 2)
void gemm_mma(const __half* __restrict__ A, const __half* __restrict__ B,
              float* __restrict__ Cf,
              __half* __restrict__ Qp, __half* __restrict__ Kp,
              __half* __restrict__ Vp)
{
    extern __shared__ char smem[];
    const uint32_t sb = smem_u32(smem);
    const int tid  = threadIdx.x;
    const int wid  = tid >> 5;
    const int lane = tid & 31;
    const int m0 = blockIdx.y * 128;
    const int n0 = blockIdx.x * 128;
    const int wm = (wid & 1) * 64;
    const int wn = (wid >> 1) * 32;
    const int w  = QKV ? (n0 >> 10) : 3;

    float acc[4][4][4];
#pragma unroll
    for (int a = 0; a < 4; a++)
#pragma unroll
        for (int b = 0; b < 4; b++)
#pragma unroll
            for (int c = 0; c < 4; c++) acc[a][b][c] = 0.f;

    stage_load(sb, 0, 0, tid, m0, n0, A, B);
    CP_COMMIT();
    stage_load(sb, 1, BKG, tid, m0, n0, A, B);
    CP_COMMIT();

    const int g = lane >> 3;
    const int r = lane & 7;

    for (int i = 0; i < NKI; i++) {
        if (i + 2 < NKI) {
            int s = i + 2; while (s >= 3) s -= 3;
            stage_load(sb, s, (i + 2) * BKG, tid, m0, n0, A, B);
            CP_COMMIT();
            CP_WAIT2();
        } else if (i + 1 < NKI) {
            CP_WAIT1();
        } else {
            CP_WAIT0();
        }
        __syncthreads();     // cross-thread visibility of stage i's cp.asyncs
        int cs = i; while (cs >= 3) cs -= 3;
        const uint32_t base = sb + (uint32_t)cs * STG;
#pragma unroll
        for (int h = 0; h < 4; h++) {
            uint32_t ah[4][4], bhf[2][4];
#pragma unroll
            for (int mi = 0; mi < 4; mi++) {
                const int arow = wm + mi * 16 + (g & 1) * 8 + r;
                const int akc  = h * 2 + (g >> 1);
                ldsm4(ah[mi][0], ah[mi][1], ah[mi][2], ah[mi][3],
                      base + 0 + fsw(arow, akc));
            }
#pragma unroll
            for (int ng = 0; ng < 2; ng++) {
                const int brow = wn + ng * 16 + (g >> 1) * 8 + r;
                const int bkc  = h * 2 + (g & 1);
                ldsm4(bhf[ng][0], bhf[ng][1], bhf[ng][2], bhf[ng][3],
                      base + 16384 + fsw(brow, bkc));
            }
#pragma unroll
            for (int mi = 0; mi < 4; mi++)
#pragma unroll
                for (int ni = 0; ni < 4; ni++) {
                    const uint32_t* bh = &bhf[ni >> 1][(ni & 1) * 2];
                    mma_f16(acc[mi][ni], ah[mi][0], ah[mi][1], ah[mi][2], ah[mi][3], bh[0], bh[1]);
                }
        }
        __syncthreads();     // all reads of this stage done before refill
    }

    // ---------------- epilogue ------------------------------------------------
    const int tg = lane >> 2;
    const int tq = lane & 3;
#pragma unroll
    for (int mi = 0; mi < 4; mi++) {
#pragma unroll
        for (int hf = 0; hf < 2; hf++) {
            const int m    = m0 + wm + mi * 16 + hf * 8 + tg;
            const int spos = m & (S_ - 1);
            const int bb   = m >> 11;
#pragma unroll
            for (int ni = 0; ni < 4; ni++) {
                const int n = n0 + wn + ni * 8 + tq * 2;     // even (global)
                float v1 = acc[mi][ni][hf * 2 + 0];
                float v2 = acc[mi][ni][hf * 2 + 1];
                if (QKV) {
                    const int nl = n & 1023;
                    const int d  = nl & (HD - 1);
                    if (w < 2) {
                        float2 cs = g_rope[spos * 32 + (d >> 1)];
                        float y1 = v1 * cs.x - v2 * cs.y;
                        float y2 = v1 * cs.y + v2 * cs.x;
                        v1 = y1; v2 = y2;
                    }
                    if (w == 0) { v1 *= QSCALE; v2 *= QSCALE; }  // log2 domain
                    const int hh = nl >> 6;
                    const size_t idx = (((size_t)(bb * H_ + hh) * S_) + spos) * HD + d;
                    __half2 hp = __floats2half2_rn(v1, v2);
                    __half* C = (w == 0) ? Qp : (w == 1) ? Kp : Vp;
                    *(__half2*)(C + idx) = hp;
                } else {
                    float* p = Cf + (size_t)m * D_ + n;
                    *(float2*)p = make_float2(v1, v2);
                }
            }
        }
    }
}

// ---------------- HMMA flash attention (causal), plain fp16 ------------------
// 128 threads (4 warps), Q tile 64 rows, K/V tiles of 128 rows, 3-stage
// pipeline (prefetch distance 2). Stage = K(16K)|V(16K) = 32KB; smem 96KB;
// 2 CTAs/SM (192KB smem, ~59K regs).
#define FSTG    32768u
#define FSMEM   (3*32768)

__device__ __forceinline__ void fa_stage(
    uint32_t base, const __half* k, const __half* v, int s0, int tid)
{
#pragma unroll
    for (int p = 0; p < 8; p++) {
        const int gi  = tid + p * 128;       // 0..1023
        const int row = gi >> 3;             // 0..127
        const int c   = gi & 7;
        const uint32_t off = fsw(row, c);
        const size_t g = (size_t)(s0 + row) * HD + c * 8;
        CP_ASYNC16(base + 0u     + off, k + g);
        CP_ASYNC16(base + 16384u + off, v + g);
    }
}

__global__ __launch_bounds__(128, 2)
void flash_mma(const __half* __restrict__ Q, const __half* __restrict__ K,
               const __half* __restrict__ V, __half* __restrict__ Oatt)
{
    extern __shared__ char smem[];
    const uint32_t sb = smem_u32(smem);
    const int tid  = threadIdx.x;
    const int wid  = tid >> 5;
    const int lane = tid & 31;
    const int bh = blockIdx.y;
    const int mt = (int)gridDim.x - 1 - (int)blockIdx.x;   // big tiles first
    const int nkt = (mt + 2) >> 1;        // 128-row K tiles covering (mt+1)*64

    const __half* qb_ = Q + ((size_t)bh * S_) * HD;
    const __half* kb_ = K + ((size_t)bh * S_) * HD;
    const __half* vb_ = V + ((size_t)bh * S_) * HD;

    const int grp = lane >> 3;
    const int rr  = lane & 7;

    // ---- stage Q (plain) through stage-0 buffer, extract frags -------------
#pragma unroll
    for (int p = 0; p < 4; p++) {
        const int gi  = tid + p * 128;       // 0..511
        const int row = gi >> 3;
        const int c   = gi & 7;
        CP_ASYNC16(sb + fsw(row, c), qb_ + (size_t)(mt * 64 + row) * HD + c * 8);
    }
    CP_COMMIT();
    CP_WAIT0();
    __syncthreads();

    uint32_t qf[4][4];
#pragma unroll
    for (int kc = 0; kc < 4; kc++) {
        const int row = wid * 16 + (grp & 1) * 8 + rr;
        const int c   = kc * 2 + (grp >> 1);
        ldsm4(qf[kc][0], qf[kc][1], qf[kc][2], qf[kc][3], sb + fsw(row, c));
    }
    __syncthreads();     // Q frags extracted before stage-0 is overwritten

    fa_stage(sb, kb_, vb_, 0, tid);
    CP_COMMIT();
    if (1 < nkt) {
        fa_stage(sb + FSTG, kb_, vb_, 128, tid);
        CP_COMMIT();
    }

    float o[8][4];
#pragma unroll
    for (int a = 0; a < 8; a++)
#pragma unroll
        for (int b = 0; b < 4; b++) o[a][b] = 0.f;
    float m0r = -1e30f, m1r = -1e30f, l0r = 0.f, l1r = 0.f;

    for (int kt = 0; kt < nkt; kt++) {
        if (kt + 2 < nkt) {
            int s = kt + 2; while (s >= 3) s -= 3;
            fa_stage(sb + (uint32_t)s * FSTG, kb_, vb_, (kt + 2) * 128, tid);
            CP_COMMIT();
            CP_WAIT2();
        } else if (kt + 1 < nkt) {
            CP_WAIT1();
        } else {
            CP_WAIT0();
        }
        __syncthreads();     // stage kt visible to all threads

        int cs = kt; while (cs >= 3) cs -= 3;
        const uint32_t st = sb + (uint32_t)cs * FSTG;

        // ---- scores S = Q K^T over 128 columns (log2 domain) -------------
        float c[16][4];
#pragma unroll
        for (int a = 0; a < 16; a++)
#pragma unroll
            for (int b = 0; b < 4; b++) c[a][b] = 0.f;

#pragma unroll
        for (int nt = 0; nt < 16; nt++) {
            const int j = nt * 8 + rr;       // K row 0..127
            uint32_t kb0[4], kb1[4];
            ldsm4(kb0[0], kb0[1], kb0[2], kb0[3], st + fsw(j, 0 + grp));
            ldsm4(kb1[0], kb1[1], kb1[2], kb1[3], st + fsw(j, 4 + grp));
            mma_f16(c[nt], qf[0][0], qf[0][1], qf[0][2], qf[0][3], kb0[0], kb0[1]);
            mma_f16(c[nt], qf[1][0], qf[1][1], qf[1][2], qf[1][3], kb0[2], kb0[3]);
            mma_f16(c[nt], qf[2][0], qf[2][1], qf[2][2], qf[2][3], kb1[0], kb1[1]);
            mma_f16(c[nt], qf[3][0], qf[3][1], qf[3][2], qf[3][3], kb1[2], kb1[3]);
        }

        // ---- causal mask on last tile (global coords) --------------------
        if (kt == nkt - 1) {
            const int ig = mt * 64 + wid * 16 + (lane >> 2);
#pragma unroll
            for (int nt = 0; nt < 16; nt++) {
                const int jg = kt * 128 + nt * 8 + (lane & 3) * 2;
                if (jg     > ig)     c[nt][0] = -1e30f;
                if (jg + 1 > ig)     c[nt][1] = -1e30f;
                if (jg     > ig + 8) c[nt][2] = -1e30f;
                if (jg + 1 > ig + 8) c[nt][3] = -1e30f;
            }
        }

        // ---- online softmax (exp2 domain) --------------------------------
        float t0 = -1e30f, t1 = -1e30f;
#pragma unroll
        for (int nt = 0; nt < 16; nt++) {
            t0 = fmaxf(t0, fmaxf(c[nt][0], c[nt][1]));
            t1 = fmaxf(t1, fmaxf(c[nt][2], c[nt][3]));
        }
        t0 = fmaxf(t0, __shfl_xor_sync(0xffffffffu, t0, 1));
        t0 = fmaxf(t0, __shfl_xor_sync(0xffffffffu, t0, 2));
        t1 = fmaxf(t1, __shfl_xor_sync(0xffffffffu, t1, 1));
        t1 = fmaxf(t1, __shfl_xor_sync(0xffffffffu, t1, 2));
        const float mn0 = fmaxf(m0r, t0);
        const float mn1 = fmaxf(m1r, t1);
        const float al0 = exp2f(m0r - mn0);
        const float al1 = exp2f(m1r - mn1);
        m0r = mn0; m1r = mn1;

        float s0 = 0.f, s1 = 0.f;
#pragma unroll
        for (int nt = 0; nt < 16; nt++) {
            c[nt][0] = exp2f(c[nt][0] - mn0);
            c[nt][1] = exp2f(c[nt][1] - mn0);
            c[nt][2] = exp2f(c[nt][2] - mn1);
            c[nt][3] = exp2f(c[nt][3] - mn1);
            s0 += c[nt][0] + c[nt][1];
            s1 += c[nt][2] + c[nt][3];
        }
        s0 += __shfl_xor_sync(0xffffffffu, s0, 1);
        s0 += __shfl_xor_sync(0xffffffffu, s0, 2);
        s1 += __shfl_xor_sync(0xffffffffu, s1, 1);
        s1 += __shfl_xor_sync(0xffffffffu, s1, 2);
        l0r = l0r * al0 + s0;
        l1r = l1r * al1 + s1;

#pragma unroll
        for (int nt = 0; nt < 8; nt++) {
            o[nt][0] *= al0; o[nt][1] *= al0;
            o[nt][2] *= al1; o[nt][3] *= al1;
        }

        // ---- O += P V (1 MMA per frag; kc 0..7 over 128 K rows) ----------
#pragma unroll
        for (int kc = 0; kc < 8; kc++) {
            uint32_t ph[4];
            const float* p0 = c[2*kc];
            const float* p1 = c[2*kc+1];
            ph[0] = pack_h2(p0[0], p0[1]);
            ph[1] = pack_h2(p0[2], p0[3]);
            ph[2] = pack_h2(p1[0], p1[1]);
            ph[3] = pack_h2(p1[2], p1[3]);
#pragma unroll
            for (int ntp = 0; ntp < 4; ntp++) {
                const int row = kc * 16 + (grp & 1) * 8 + rr;   // V row 0..127
                const int ch  = ntp * 2 + (grp >> 1);
                uint32_t v0, v1, v2, v3;
                ldsm4t(v0, v1, v2, v3, st + 16384u + fsw(row, ch));
                mma_f16(o[2*ntp],   ph[0], ph[1], ph[2], ph[3], v0, v1);
                mma_f16(o[2*ntp+1], ph[0], ph[1], ph[2], ph[3], v2, v3);
            }
        }
        __syncthreads();     // all reads of this buffer done before refill
    }

    // ---- finalize + write plain fp16 [B,S,D] --------------------------------
    const float inv0 = 1.f / l0r;
    const float inv1 = 1.f / l1r;
    const int b = bh >> 4;
    const int h = bh & (H_ - 1);
    const int sq0 = mt * 64 + wid * 16 + (lane >> 2);
    const size_t base0 = ((size_t)(b * S_ + sq0)) * D_ + h * HD;
    const size_t base1 = base0 + (size_t)8 * D_;
#pragma unroll
    for (int nt = 0; nt < 8; nt++) {
        const int col = nt * 8 + (lane & 3) * 2;
        {
            __half2 hp = __floats2half2_rn(o[nt][0] * inv0, o[nt][1] * inv0);
            *(__half2*)(Oatt + base0 + col) = hp;
        }
        {
            __half2 hp = __floats2half2_rn(o[nt][2] * inv1, o[nt][3] * inv1);
            *(__half2*)(Oatt + base1 + col) = hp;
        }
    }
}

// ---------------- launch -----------------------------------------------------
extern "C" void kernel_launch(void* const* d_in, const int* in_sizes, int n_in,
                              void* d_out, int out_size)
{
    const float* x  = (const float*)d_in[0];
    float* out = (float*)d_out;

    void *pq, *pk, *pv, *pxh, *pwh, *patt, *prope;
    cudaGetSymbolAddress(&pq,  g_q);
    cudaGetSymbolAddress(&pk,  g_k);
    cudaGetSymbolAddress(&pv,  g_v);
    cudaGetSymbolAddress(&pxh, g_xh);
    cudaGetSymbolAddress(&pwh, g_wh);
    cudaGetSymbolAddress(&patt, g_att);
    cudaGetSymbolAddress(&prope, g_rope);

    cudaFuncSetAttribute(gemm_mma<1>, cudaFuncAttributeMaxDynamicSharedMemorySize, GSMEM);
    cudaFuncSetAttribute(gemm_mma<0>, cudaFuncAttributeMaxDynamicSharedMemorySize, GSMEM);
    cudaFuncSetAttribute(flash_mma, cudaFuncAttributeMaxDynamicSharedMemorySize, FSMEM);

    __half* xh = (__half*)pxh;
    __half* wh = (__half*)pwh;

    // fused fp32->fp16 converts + RoPE table (one launch)
    split_all<<<(NCVT + NROPE + 255) / 256, 256>>>(
        x, (const float*)d_in[1], (const float*)d_in[2],
        (const float*)d_in[3], (const float*)d_in[4],
        xh, wh, (float2*)prope);

    // fused QKV projection -> plain fp16 [B,H,S,hd]
    dim3 qkvgrid(3 * D_ / 128, MTOT / 128);   // (24, 32)
    gemm_mma<1><<<qkvgrid, 256, GSMEM>>>(xh, wh, nullptr,
        (__half*)pq, (__half*)pk, (__half*)pv);

    // tensor-core causal flash attention -> plain fp16 [B,S,D]
    dim3 agrid(S_ / 64, B_ * H_);        // (32, 32), 2 CTAs/SM
    flash_mma<<<agrid, 128, FSMEM>>>((const __half*)pq, (const __half*)pk,
                                     (const __half*)pv, (__half*)patt);

    // output projection -> d_out (fp32)
    dim3 ogrid(D_ / 128, MTOT / 128);    // (8, 32)
    gemm_mma<0><<<ogrid, 256, GSMEM>>>((const __half*)patt,
                                       wh + 3*(size_t)D_*D_,
                                       out, nullptr, nullptr, nullptr);
}